// round 5
// baseline (speedup 1.0000x reference)
#include <cuda_runtime.h>
#include <cstdint>

#define Bb 16
#define Nn 16
#define Hh 512
#define Ww 512
#define HW  (Hh * Ww)
#define HW4 (HW / 4)                 // 65536 float4 per slice
#define THREADS 256
#define NG 4                         // masks per stream block
#define NGROUPS (Nn / NG)            // 4
#define SPLIT 16
#define CHUNK_F4 (HW4 / SPLIT)       // 4096 float4
#define ITER (CHUNK_F4 / THREADS)    // 16
#define GRID_A (Bb * NGROUPS * SPLIT)  // 1024 stream blocks
#define GRID_T (GRID_A + Bb * Nn)      // + 256 box blocks

__device__ float    g_ov[Bb * Nn];
__device__ float    g_it[Bb * Nn];
__device__ float    g_ts[Bb];
__device__ unsigned g_done;

__global__ __launch_bounds__(THREADS, 5)
void fused3_kernel(const float* __restrict__ masks,
                   const float* __restrict__ target,
                   const int*   __restrict__ boxes,
                   float*       __restrict__ out)
{
    const int tid = threadIdx.x;
    const int wid = tid >> 5;
    const int lid = tid & 31;
    const unsigned FULL = 0xFFFFFFFFu;
    __shared__ float s_red[THREADS / 32][5];

    if (blockIdx.x < GRID_A) {
        // ================= stream blocks: ov + ts =================
        const int blk   = blockIdx.x;
        const int b     = blk >> 6;
        const int rest  = blk & 63;
        const int ng    = rest >> 4;        // mask group
        const int split = rest & 15;        // chunk

        const size_t coff = (size_t)split * CHUNK_F4;
        const float4* __restrict__ t  = (const float4*)target + (size_t)b * HW4 + coff;
        const float4* __restrict__ m0 = (const float4*)masks + ((size_t)(b * Nn + ng * NG + 0)) * HW4 + coff;
        const float4* __restrict__ m1 = (const float4*)masks + ((size_t)(b * Nn + ng * NG + 1)) * HW4 + coff;
        const float4* __restrict__ m2 = (const float4*)masks + ((size_t)(b * Nn + ng * NG + 2)) * HW4 + coff;
        const float4* __restrict__ m3 = (const float4*)masks + ((size_t)(b * Nn + ng * NG + 3)) * HW4 + coff;

        float ov0 = 0.f, ov1 = 0.f, ov2 = 0.f, ov3 = 0.f, ts = 0.f;

        #pragma unroll 4
        for (int k = 0; k < ITER; k++) {
            const int idx = tid + k * THREADS;
            const float4 tv = t[idx];
            const float4 v0 = m0[idx];
            const float4 v1 = m1[idx];
            const float4 v2 = m2[idx];
            const float4 v3 = m3[idx];

            ts += (tv.x + tv.y) + (tv.z + tv.w);

            ov0 = fmaf(v0.x, tv.x, ov0); ov0 = fmaf(v0.y, tv.y, ov0);
            ov0 = fmaf(v0.z, tv.z, ov0); ov0 = fmaf(v0.w, tv.w, ov0);
            ov1 = fmaf(v1.x, tv.x, ov1); ov1 = fmaf(v1.y, tv.y, ov1);
            ov1 = fmaf(v1.z, tv.z, ov1); ov1 = fmaf(v1.w, tv.w, ov1);
            ov2 = fmaf(v2.x, tv.x, ov2); ov2 = fmaf(v2.y, tv.y, ov2);
            ov2 = fmaf(v2.z, tv.z, ov2); ov2 = fmaf(v2.w, tv.w, ov2);
            ov3 = fmaf(v3.x, tv.x, ov3); ov3 = fmaf(v3.y, tv.y, ov3);
            ov3 = fmaf(v3.z, tv.z, ov3); ov3 = fmaf(v3.w, tv.w, ov3);
        }

        float v[5] = {ov0, ov1, ov2, ov3, ts};
        #pragma unroll
        for (int q = 0; q < 5; q++) {
            #pragma unroll
            for (int off = 16; off > 0; off >>= 1)
                v[q] += __shfl_xor_sync(FULL, v[q], off);
        }
        if (lid == 0) {
            #pragma unroll
            for (int q = 0; q < 5; q++) s_red[wid][q] = v[q];
        }
        __syncthreads();

        if (tid < 5) {
            float sum = 0.f;
            #pragma unroll
            for (int w = 0; w < THREADS / 32; w++) sum += s_red[w][tid];
            if (tid < 4) {
                atomicAdd(&g_ov[b * Nn + ng * NG + tid], sum);
            } else if (ng == 0) {   // ts counted once per (b, chunk)
                atomicAdd(&g_ts[b], sum);
            }
        }
    } else {
        // ================= box blocks: intersection =================
        const int bn = blockIdx.x - GRID_A;     // 0..255
        const int b  = bn >> 4;
        const int4 bx = __ldg((const int4*)boxes + bn);
        const int x1 = bx.x, y1 = bx.y, x2 = bx.z, y2 = bx.w;

        const float* __restrict__ t = target + (size_t)b * HW;
        float it = 0.f;
        const int bw = x2 - x1;
        const int total = (y2 - y1) * bw;
        for (int i = tid; i < total; i += THREADS) {
            const int h = y1 + i / bw;
            const int w = x1 + i % bw;
            it += __ldg(t + h * Ww + w);
        }

        #pragma unroll
        for (int off = 16; off > 0; off >>= 1)
            it += __shfl_xor_sync(FULL, it, off);
        if (lid == 0) s_red[wid][0] = it;
        __syncthreads();
        if (tid == 0) {
            float sum = 0.f;
            #pragma unroll
            for (int w = 0; w < THREADS / 32; w++) sum += s_red[w][0];
            g_it[bn] = sum;     // one writer per bn; plain store
        }
    }

    __threadfence();
    __syncthreads();

    __shared__ unsigned s_last;
    if (tid == 0) s_last = atomicAdd(&g_done, 1u);
    __syncthreads();

    // ---- last block finalizes + resets ----
    if (s_last == GRID_T - 1) {
        const int bn = tid;   // 0..255
        const float ovv = *(volatile float*)&g_ov[bn];
        const float itv = *(volatile float*)&g_it[bn];
        const float tsv = *(volatile float*)&g_ts[bn >> 4];
        const int4 bx = reinterpret_cast<const int4*>(boxes)[bn];
        const float area = (float)(bx.z - bx.x) * (float)(bx.w - bx.y);
        const float uni = area + tsv - itv;
        out[bn * 2 + 0] = ovv;
        out[bn * 2 + 1] = itv / (uni + 1e-8f);
        g_ov[bn] = 0.f;
        if (bn < Bb) g_ts[bn] = 0.f;
        if (bn == 0) g_done = 0u;
    }
}

extern "C" void kernel_launch(void* const* d_in, const int* in_sizes, int n_in,
                              void* d_out, int out_size)
{
    const float* masks  = (const float*)d_in[0];   // (B,N,H,W) f32
    const float* target = (const float*)d_in[1];   // (B,H,W)   f32
    const int*   boxes  = (const int*)d_in[2];     // (B,N,4)   i32
    float* out = (float*)d_out;                    // (B,N,2)   f32

    fused3_kernel<<<GRID_T, THREADS>>>(masks, target, boxes, out);
}